// round 1
// baseline (speedup 1.0000x reference)
#include <cuda_runtime.h>
#include <math.h>

// Problem constants (fixed by reference setup_inputs)
#define B_ROWS 16384
#define C_CLS  1000
#define NNODES 4096
#define NEDGES 131072

#define RES_BLOCKS 512
#define RES_THREADS 256

__device__ float g_ce_partials[B_ROWS];
__device__ float g_res_partials[RES_BLOCKS];

static __device__ __forceinline__ void combine_ms(float& m, float& s, float m2, float s2) {
    float M = fmaxf(m, m2);
    s = s * __expf(m - M) + s2 * __expf(m2 - M);
    m = M;
}

// One 128-thread block per row. Online softmax (single pass over the row).
__global__ __launch_bounds__(128) void ce_kernel(const float* __restrict__ outputs,
                                                 const int* __restrict__ targets) {
    const int row = blockIdx.x;
    const float4* __restrict__ rp =
        reinterpret_cast<const float4*>(outputs + (size_t)row * C_CLS);

    float m = -INFINITY, s = 0.0f;
    const int t = threadIdx.x;
    // 1000 floats = 250 float4 per row
    #pragma unroll
    for (int i = t; i < 250; i += 128) {
        float4 v = rp[i];
        float lm = fmaxf(fmaxf(v.x, v.y), fmaxf(v.z, v.w));
        float M = fmaxf(m, lm);
        s = s * __expf(m - M)
            + __expf(v.x - M) + __expf(v.y - M)
            + __expf(v.z - M) + __expf(v.w - M);
        m = M;
    }

    // warp reduce (m, s)
    #pragma unroll
    for (int off = 16; off > 0; off >>= 1) {
        float m2 = __shfl_down_sync(0xFFFFFFFFu, m, off);
        float s2 = __shfl_down_sync(0xFFFFFFFFu, s, off);
        combine_ms(m, s, m2, s2);
    }

    __shared__ float sm_m[4], sm_s[4];
    const int warp = t >> 5, lane = t & 31;
    if (lane == 0) { sm_m[warp] = m; sm_s[warp] = s; }
    __syncthreads();

    if (t == 0) {
        float M = sm_m[0], S = sm_s[0];
        #pragma unroll
        for (int w = 1; w < 4; w++) combine_ms(M, S, sm_m[w], sm_s[w]);
        int tgt = targets[row];
        float xt = outputs[(size_t)row * C_CLS + tgt];
        // -log_softmax[target] = -(x_t - M - log(S))
        g_ce_partials[row] = -(xt - M - __logf(S));
    }
}

// One edge per thread (512*256 = 131072). Two scattered gathers per edge.
__global__ __launch_bounds__(RES_THREADS) void res_kernel(const float* __restrict__ P,
                                                          const int* __restrict__ src,
                                                          const int* __restrict__ dst) {
    const float TWO_PI_F = 6.2831853071795864769f;
    const float PI_F     = 3.1415926535897932385f;

    const int e = blockIdx.x * RES_THREADS + threadIdx.x;
    int si = src[e];
    int di = dst[e];
    float a = __ldg(&P[(size_t)si * NNODES + di]);
    float b = __ldg(&P[(size_t)di * NNODES + si]);
    float d = fabsf(a - b);
    d = fmodf(d, TWO_PI_F);
    if (d > PI_F) d = TWO_PI_F - d;

    // block reduce
    #pragma unroll
    for (int off = 16; off > 0; off >>= 1)
        d += __shfl_down_sync(0xFFFFFFFFu, d, off);

    __shared__ float sm[RES_THREADS / 32];
    const int warp = threadIdx.x >> 5, lane = threadIdx.x & 31;
    if (lane == 0) sm[warp] = d;
    __syncthreads();
    if (threadIdx.x == 0) {
        float acc = 0.0f;
        #pragma unroll
        for (int w = 0; w < RES_THREADS / 32; w++) acc += sm[w];
        g_res_partials[blockIdx.x] = acc;
    }
}

__global__ __launch_bounds__(256) void finalize_kernel(float* __restrict__ out) {
    // per-thread partial: fold CE and resonance with their final weights
    float acc = 0.0f;
    for (int i = threadIdx.x; i < B_ROWS; i += 256) acc += g_ce_partials[i];
    float racc = 0.0f;
    for (int i = threadIdx.x; i < RES_BLOCKS; i += 256) racc += g_res_partials[i];

    float v = acc * (1.0f / B_ROWS) + 0.1f * racc * (1.0f / NEDGES);

    __shared__ float red[256];
    red[threadIdx.x] = v;
    __syncthreads();
    #pragma unroll
    for (int stride = 128; stride > 0; stride >>= 1) {
        if (threadIdx.x < stride) red[threadIdx.x] += red[threadIdx.x + stride];
        __syncthreads();
    }
    if (threadIdx.x == 0) out[0] = red[0];
}

extern "C" void kernel_launch(void* const* d_in, const int* in_sizes, int n_in,
                              void* d_out, int out_size) {
    const float* outputs = (const float*)d_in[0];
    const int*   targets = (const int*)d_in[1];
    const float* phase   = (const float*)d_in[2];
    const int*   esrc    = (const int*)d_in[3];
    const int*   edst    = (const int*)d_in[4];
    float* out = (float*)d_out;

    ce_kernel<<<B_ROWS, 128>>>(outputs, targets);
    res_kernel<<<RES_BLOCKS, RES_THREADS>>>(phase, esrc, edst);
    finalize_kernel<<<1, 256>>>(out);
}

// round 2
// speedup vs baseline: 1.4140x; 1.4140x over previous
#include <cuda_runtime.h>
#include <math.h>

#define B_ROWS 16384
#define C_CLS  1000
#define NNODES 4096
#define NEDGES 131072

#define CE_BLOCKS   2048           // 8 rows (warps) per block
#define RES_BLOCKS  512            // 256 edges per block
#define TOTAL_BLOCKS (CE_BLOCKS + RES_BLOCKS)

__device__ float g_ce_partials[CE_BLOCKS];
__device__ float g_res_partials[RES_BLOCKS];

__global__ __launch_bounds__(256) void fused_kernel(const float* __restrict__ outputs,
                                                    const int* __restrict__ targets,
                                                    const float* __restrict__ P,
                                                    const int* __restrict__ src,
                                                    const int* __restrict__ dst) {
    const int t = threadIdx.x;
    const int lane = t & 31;
    const int warp = t >> 5;

    if (blockIdx.x < CE_BLOCKS) {
        // ---------------- CE: one warp per row ----------------
        const int row = blockIdx.x * 8 + warp;
        const float* rowp = outputs + (size_t)row * C_CLS;
        const float4* __restrict__ rp = reinterpret_cast<const float4*>(rowp);

        // prefetch target logit (dependent gather) early
        const int tgt = __ldg(&targets[row]);
        const float xt = __ldg(&rowp[tgt]);

        // batched front loads: 250 float4 per row, lane handles lane+32k
        float4 v[8];
        #pragma unroll
        for (int k = 0; k < 7; k++) v[k] = rp[lane + 32 * k];
        const bool tail_ok = (lane + 224) < 250;   // 250 = 7*32 + 26
        v[7] = tail_ok ? rp[lane + 224]
                       : make_float4(-INFINITY, -INFINITY, -INFINITY, -INFINITY);

        // pass A: max
        float m = -INFINITY;
        #pragma unroll
        for (int k = 0; k < 8; k++)
            m = fmaxf(m, fmaxf(fmaxf(v[k].x, v[k].y), fmaxf(v[k].z, v[k].w)));
        #pragma unroll
        for (int off = 16; off > 0; off >>= 1)
            m = fmaxf(m, __shfl_xor_sync(0xFFFFFFFFu, m, off));

        // pass B: sum of exp (exp(-inf - m) -> 0 handles tail)
        float s = 0.0f;
        #pragma unroll
        for (int k = 0; k < 8; k++) {
            s += __expf(v[k].x - m) + __expf(v[k].y - m)
               + __expf(v[k].z - m) + __expf(v[k].w - m);
        }
        #pragma unroll
        for (int off = 16; off > 0; off >>= 1)
            s += __shfl_xor_sync(0xFFFFFFFFu, s, off);

        __shared__ float sm[8];
        if (lane == 0) sm[warp] = -(xt - m - __logf(s));
        __syncthreads();
        if (t == 0) {
            float acc = 0.0f;
            #pragma unroll
            for (int w = 0; w < 8; w++) acc += sm[w];
            g_ce_partials[blockIdx.x] = acc;
        }
    } else {
        // ---------------- resonance: one edge per thread ----------------
        const float TWO_PI_F = 6.2831853071795864769f;
        const float PI_F     = 3.1415926535897932385f;

        const int e = (blockIdx.x - CE_BLOCKS) * 256 + t;
        const int si = __ldg(&src[e]);
        const int di = __ldg(&dst[e]);
        float a = __ldg(&P[(size_t)si * NNODES + di]);
        float b = __ldg(&P[(size_t)di * NNODES + si]);
        float d = fabsf(a - b);
        d = fmodf(d, TWO_PI_F);
        if (d > PI_F) d = TWO_PI_F - d;

        #pragma unroll
        for (int off = 16; off > 0; off >>= 1)
            d += __shfl_down_sync(0xFFFFFFFFu, d, off);

        __shared__ float sm[8];
        if (lane == 0) sm[warp] = d;
        __syncthreads();
        if (t == 0) {
            float acc = 0.0f;
            #pragma unroll
            for (int w = 0; w < 8; w++) acc += sm[w];
            g_res_partials[blockIdx.x - CE_BLOCKS] = acc;
        }
    }
}

__global__ __launch_bounds__(256) void finalize_kernel(float* __restrict__ out) {
    float ce = 0.0f, rs = 0.0f;
    for (int i = threadIdx.x; i < CE_BLOCKS; i += 256) ce += g_ce_partials[i];
    for (int i = threadIdx.x; i < RES_BLOCKS; i += 256) rs += g_res_partials[i];
    float v = ce * (1.0f / B_ROWS) + 0.1f * rs * (1.0f / NEDGES);

    __shared__ float red[256];
    red[threadIdx.x] = v;
    __syncthreads();
    #pragma unroll
    for (int stride = 128; stride > 0; stride >>= 1) {
        if (threadIdx.x < stride) red[threadIdx.x] += red[threadIdx.x + stride];
        __syncthreads();
    }
    if (threadIdx.x == 0) out[0] = red[0];
}

extern "C" void kernel_launch(void* const* d_in, const int* in_sizes, int n_in,
                              void* d_out, int out_size) {
    const float* outputs = (const float*)d_in[0];
    const int*   targets = (const int*)d_in[1];
    const float* phase   = (const float*)d_in[2];
    const int*   esrc    = (const int*)d_in[3];
    const int*   edst    = (const int*)d_in[4];
    float* out = (float*)d_out;

    fused_kernel<<<TOTAL_BLOCKS, 256>>>(outputs, targets, phase, esrc, edst);
    finalize_kernel<<<1, 256>>>(out);
}